// round 2
// baseline (speedup 1.0000x reference)
#include <cuda_runtime.h>
#include <cstdint>

// ---------------------------------------------------------------------------
// GRUBlock: 2-layer bidirectional GRU (B=16, H=256, T=2048) + LN + FFN
// fp32 throughout; f32x2 packed FMA for 2x fp32 rate on sm_103a.
// ---------------------------------------------------------------------------

#define BATCH 16
#define CH    256
#define SEQ   2048
#define HID   256
#define G3    768           // 3*H gate rows
#define M_ROWS (BATCH*SEQ)  // 32768 tokens

typedef unsigned long long ull;

__device__ __forceinline__ ull pack2(float x, float y) {
    ull r; asm("mov.b64 %0,{%1,%2};" : "=l"(r) : "f"(x), "f"(y)); return r;
}
__device__ __forceinline__ void unpack2(ull v, float& x, float& y) {
    asm("mov.b64 {%0,%1},%2;" : "=f"(x), "=f"(y) : "l"(v));
}
__device__ __forceinline__ ull fma2(ull a, ull b, ull c) {
    ull d; asm("fma.rn.f32x2 %0,%1,%2,%3;" : "=l"(d) : "l"(a), "l"(b), "l"(c)); return d;
}

// ----------------------------- scratch (static device memory) --------------
__device__ float g_gi  [(size_t)2 * BATCH * SEQ * G3];     // gate pre-activations, both dirs (reused per layer; also final y)
__device__ float g_bufA[(size_t)BATCH * SEQ * 2 * HID];    // layer0 output (B,T,512); later FFN mid (32768,512)
__device__ float g_bufB[(size_t)BATCH * SEQ * 2 * HID];    // layer1 output (B,T,512)
__device__ float g_bufC[(size_t)BATCH * SEQ * HID];        // xT (B,T,C); later ln_out (32768,256)

// ----------------------------- transpose: (B,D1,D2) -> (B,D2,D1) -----------
__global__ void transpose_k(const float* __restrict__ src, float* __restrict__ dst,
                            int D1, int D2)
{
    __shared__ float tile[32][33];
    const int b  = blockIdx.z;
    const int j0 = blockIdx.x * 32;   // along D2
    const int i0 = blockIdx.y * 32;   // along D1
    const float* s = src + (size_t)b * D1 * D2;
    float*       d = dst + (size_t)b * D1 * D2;
    #pragma unroll
    for (int r = 0; r < 32; r += 8)
        tile[threadIdx.y + r][threadIdx.x] =
            s[(size_t)(i0 + threadIdx.y + r) * D2 + j0 + threadIdx.x];
    __syncthreads();
    #pragma unroll
    for (int r = 0; r < 32; r += 8)
        d[(size_t)(j0 + threadIdx.y + r) * D1 + i0 + threadIdx.x] =
            tile[threadIdx.x][threadIdx.y + r];
}

// ----------------------------- SGEMM: C[m][n] = sum_k A[m][k]*B[n][k] + bias[n]
// A (M,K) row-major, Bw (N,K) row-major. 128x128 tile, BK=16, 256 thr, 8x8/thr,
// inner product via fma.rn.f32x2. M,N multiples of 128; K multiple of 16.
__global__ void __launch_bounds__(256, 2)
gemm_kernel(const float* __restrict__ A, const float* __restrict__ Bw,
            const float* __restrict__ bias, float* __restrict__ C,
            int M, int N, int K, int relu)
{
    __shared__ float As[16][128];
    __shared__ float Bs[16][128];
    const int tid = threadIdx.x;
    const int tx = tid & 15, ty = tid >> 4;
    const float* Ab = A  + (size_t)blockIdx.y * 128 * K;
    const float* Bb = Bw + (size_t)blockIdx.x * 128 * K;
    const int lrow = tid >> 1;
    const int lq   = (tid & 1) * 2;

    ull c2[8][4];
    #pragma unroll
    for (int i = 0; i < 8; i++)
        #pragma unroll
        for (int j = 0; j < 4; j++) c2[i][j] = 0ull;

    for (int kt = 0; kt < K; kt += 16) {
        #pragma unroll
        for (int q0 = 0; q0 < 2; q0++) {
            const int q = lq + q0;
            float4 va = *(const float4*)&Ab[(size_t)lrow * K + kt + q * 4];
            As[q*4+0][lrow] = va.x; As[q*4+1][lrow] = va.y;
            As[q*4+2][lrow] = va.z; As[q*4+3][lrow] = va.w;
            float4 vb = *(const float4*)&Bb[(size_t)lrow * K + kt + q * 4];
            Bs[q*4+0][lrow] = vb.x; Bs[q*4+1][lrow] = vb.y;
            Bs[q*4+2][lrow] = vb.z; Bs[q*4+3][lrow] = vb.w;
        }
        __syncthreads();
        #pragma unroll
        for (int k = 0; k < 16; k++) {
            float4 a0 = *(const float4*)&As[k][ty * 8];
            float4 a1 = *(const float4*)&As[k][ty * 8 + 4];
            float4 b0 = *(const float4*)&Bs[k][tx * 8];
            float4 b1 = *(const float4*)&Bs[k][tx * 8 + 4];
            ull bp[4] = { pack2(b0.x, b0.y), pack2(b0.z, b0.w),
                          pack2(b1.x, b1.y), pack2(b1.z, b1.w) };
            float av[8] = { a0.x, a0.y, a0.z, a0.w, a1.x, a1.y, a1.z, a1.w };
            #pragma unroll
            for (int i = 0; i < 8; i++) {
                ull as = pack2(av[i], av[i]);
                #pragma unroll
                for (int j = 0; j < 4; j++) c2[i][j] = fma2(as, bp[j], c2[i][j]);
            }
        }
        __syncthreads();
    }
    const int n0 = blockIdx.x * 128 + tx * 8;
    float bv[8];
    #pragma unroll
    for (int j = 0; j < 8; j++) bv[j] = bias[n0 + j];
    #pragma unroll
    for (int i = 0; i < 8; i++) {
        float o[8];
        #pragma unroll
        for (int j = 0; j < 4; j++) unpack2(c2[i][j], o[2*j], o[2*j+1]);
        #pragma unroll
        for (int j = 0; j < 8; j++) {
            o[j] += bv[j];
            if (relu) o[j] = fmaxf(o[j], 0.f);
        }
        float* cp = &C[((size_t)blockIdx.y * 128 + ty * 8 + i) * N + n0];
        *(float4*)cp       = make_float4(o[0], o[1], o[2], o[3]);
        *(float4*)(cp + 4) = make_float4(o[4], o[5], o[6], o[7]);
    }
}

// ----------------------------- GRU scan ------------------------------------
// One cluster of 4 CTAs per (batch,dir) chain. CTA ci owns hidden units
// j in [ci*64, ci*64+64): gate rows {j, 256+j, 512+j} of w_hh, all 192x256
// weights held in registers (64 f32x2 per thread, 384 threads).
// Per step: gh = h @ Wslice^T (f32x2 dot, broadcast LDS of h), smem reduce
// across the 2 k-halves, gate math on 64 threads, broadcast h_new to all
// 4 CTAs' next-parity h buffer via st.shared::cluster, barrier.cluster.
#define SPLIT 4
#define STH   384

__global__ void __launch_bounds__(STH, 1) __cluster_dims__(SPLIT, 1, 1)
scan_kernel(const float* __restrict__ gi,
            const float* __restrict__ whh_f, const float* __restrict__ bhh_f,
            const float* __restrict__ whh_b, const float* __restrict__ bhh_b,
            float* __restrict__ out)
{
    const int ci    = blockIdx.x;        // rank within cluster (cluster spans x)
    const int chain = blockIdx.y;        // 0..31
    const int b     = chain & (BATCH - 1);
    const int dir   = chain >> 4;
    const float* whh = dir ? whh_b : whh_f;
    const float* bhh = dir ? bhh_b : bhh_f;
    const float* giB = gi + ((size_t)dir * BATCH + b) * (size_t)SEQ * G3;
    float* outB = out + (size_t)b * SEQ * (2 * HID) + dir * HID;

    const int tid  = threadIdx.x;
    const int g    = tid / 192;          // k half: 0 -> k[0,128), 1 -> k[128,256)
    const int o    = tid % 192;          // output row within slice
    const int gate = o >> 6;             // 0=r 1=z 2=n
    const int jl   = o & 63;
    const int row  = gate * HID + ci * 64 + jl;

    __shared__ float hbuf[2][HID];
    __shared__ float part[STH];

    // weights into registers
    ull wreg[64];
    {
        const ull* wp = (const ull*)(whh + (size_t)row * HID + g * 128);
        #pragma unroll
        for (int i = 0; i < 64; i++) wreg[i] = wp[i];
    }
    const float bias = (g == 0) ? bhh[row] : 0.f;

    for (int i = tid; i < 2 * HID; i += STH) (&hbuf[0][0])[i] = 0.f;
    __syncthreads();
    asm volatile("barrier.cluster.arrive.aligned;" ::: "memory");
    asm volatile("barrier.cluster.wait.aligned;"   ::: "memory");

    uint32_t hb_addr0;
    asm("{ .reg .u64 t; cvta.to.shared.u64 t, %1; cvt.u32.u64 %0, t; }"
        : "=r"(hb_addr0) : "l"(&hbuf[0][0]));

    // prefetch gi for step 0 (only the 64 gate-combining threads need it)
    float p_r = 0.f, p_z = 0.f, p_n = 0.f;
    if (tid < 64) {
        const float* gp = giB + (size_t)(dir ? SEQ - 1 : 0) * G3 + ci * 64 + tid;
        p_r = __ldg(gp); p_z = __ldg(gp + HID); p_n = __ldg(gp + 2 * HID);
    }

    for (int s = 0; s < SEQ; s++) {
        const int t = dir ? (SEQ - 1 - s) : s;
        const int p = s & 1;
        const float gi_r = p_r, gi_z = p_z, gi_n = p_n;
        if (tid < 64 && s + 1 < SEQ) {
            const int tn = dir ? (SEQ - 2 - s) : (s + 1);
            const float* gp = giB + (size_t)tn * G3 + ci * 64 + tid;
            p_r = __ldg(gp); p_z = __ldg(gp + HID); p_n = __ldg(gp + 2 * HID);
        }

        // 128-long dot over this thread's k half
        ull acc0 = pack2(bias, 0.f);
        ull acc1 = pack2(0.f, 0.f);
        const float4* h4 = (const float4*)&hbuf[p][g * 128];
        #pragma unroll
        for (int kk = 0; kk < 32; kk++) {
            float4 hv = h4[kk];
            acc0 = fma2(wreg[2*kk],     pack2(hv.x, hv.y), acc0);
            acc1 = fma2(wreg[2*kk + 1], pack2(hv.z, hv.w), acc1);
        }
        float aa, bb, cc, dd;
        unpack2(acc0, aa, bb); unpack2(acc1, cc, dd);
        part[tid] = (aa + cc) + (bb + dd);
        __syncthreads();

        if (tid < 64) {
            const float gh_r = part[tid]       + part[192 + tid];
            const float gh_z = part[64 + tid]  + part[256 + tid];
            const float gh_n = part[128 + tid] + part[320 + tid];
            const float r = 1.f / (1.f + expf(-(gi_r + gh_r)));
            const float z = 1.f / (1.f + expf(-(gi_z + gh_z)));
            const float n = tanhf(gi_n + r * gh_n);
            const float hold = hbuf[p][ci * 64 + tid];
            const float hnew = (1.f - z) * n + z * hold;
            outB[(size_t)t * (2 * HID) + ci * 64 + tid] = hnew;
            // broadcast to all 4 CTAs' next-parity h buffer
            const uint32_t dstoff = hb_addr0 + (uint32_t)((p ^ 1) * HID + ci * 64 + tid) * 4u;
            #pragma unroll
            for (int peer = 0; peer < SPLIT; peer++) {
                uint32_t ra;
                asm volatile("mapa.shared::cluster.u32 %0, %1, %2;"
                             : "=r"(ra) : "r"(dstoff), "r"(peer));
                asm volatile("st.shared::cluster.f32 [%0], %1;"
                             :: "r"(ra), "f"(hnew) : "memory");
            }
        }
        // cluster barrier: orders DSMEM stores (release/acquire) + step lockstep
        asm volatile("barrier.cluster.arrive.aligned;" ::: "memory");
        asm volatile("barrier.cluster.wait.aligned;"   ::: "memory");
    }
}

// ----------------------------- sum dirs + LayerNorm ------------------------
__global__ void sum_ln_kernel(const float* __restrict__ in,
                              const float* __restrict__ gw,
                              const float* __restrict__ bw,
                              float* __restrict__ out)
{
    const int lane = threadIdx.x & 31;
    const size_t row = (size_t)blockIdx.x * 8 + (threadIdx.x >> 5);
    const float* r = in + row * 512;
    float v[8]; float s = 0.f, s2 = 0.f;
    #pragma unroll
    for (int i = 0; i < 8; i++) {
        int c = i * 32 + lane;
        v[i] = r[c] + r[256 + c];
        s += v[i]; s2 += v[i] * v[i];
    }
    #pragma unroll
    for (int off = 16; off; off >>= 1) {
        s  += __shfl_xor_sync(~0u, s,  off);
        s2 += __shfl_xor_sync(~0u, s2, off);
    }
    const float mu  = s * (1.f / 256.f);
    const float var = s2 * (1.f / 256.f) - mu * mu;
    const float inv = rsqrtf(var + 1e-5f);
    float* op = out + row * 256;
    #pragma unroll
    for (int i = 0; i < 8; i++) {
        int c = i * 32 + lane;
        op[c] = (v[i] - mu) * inv * gw[c] + bw[c];
    }
}

// ----------------------------- orchestration -------------------------------
extern "C" void kernel_launch(void* const* d_in, const int* in_sizes, int n_in,
                              void* d_out, int out_size)
{
    (void)in_sizes; (void)n_in; (void)out_size;
    const float* x      = (const float*)d_in[0];
    const float* w_ih0f = (const float*)d_in[1];
    const float* w_hh0f = (const float*)d_in[2];
    const float* b_ih0f = (const float*)d_in[3];
    const float* b_hh0f = (const float*)d_in[4];
    const float* w_ih0b = (const float*)d_in[5];
    const float* w_hh0b = (const float*)d_in[6];
    const float* b_ih0b = (const float*)d_in[7];
    const float* b_hh0b = (const float*)d_in[8];
    const float* w_ih1f = (const float*)d_in[9];
    const float* w_hh1f = (const float*)d_in[10];
    const float* b_ih1f = (const float*)d_in[11];
    const float* b_hh1f = (const float*)d_in[12];
    const float* w_ih1b = (const float*)d_in[13];
    const float* w_hh1b = (const float*)d_in[14];
    const float* b_ih1b = (const float*)d_in[15];
    const float* b_hh1b = (const float*)d_in[16];
    const float* ln_g   = (const float*)d_in[17];
    const float* ln_b   = (const float*)d_in[18];
    const float* w1     = (const float*)d_in[19];
    const float* b1     = (const float*)d_in[20];
    const float* w2     = (const float*)d_in[21];
    const float* b2     = (const float*)d_in[22];

    float *gi, *bufA, *bufB, *bufC;
    cudaGetSymbolAddress((void**)&gi,   g_gi);
    cudaGetSymbolAddress((void**)&bufA, g_bufA);
    cudaGetSymbolAddress((void**)&bufB, g_bufB);
    cudaGetSymbolAddress((void**)&bufC, g_bufC);

    const dim3 tb(32, 8);
    const dim3 gemm_grid(G3 / 128, M_ROWS / 128);

    // x (B,C,L) -> xT (B,L,C)
    transpose_k<<<dim3(SEQ / 32, CH / 32, BATCH), tb>>>(x, bufC, CH, SEQ);

    // layer 0 input gates
    gemm_kernel<<<gemm_grid, 256>>>(bufC, w_ih0f, b_ih0f, gi,                        M_ROWS, G3, CH, 0);
    gemm_kernel<<<gemm_grid, 256>>>(bufC, w_ih0b, b_ih0b, gi + (size_t)M_ROWS * G3,  M_ROWS, G3, CH, 0);

    // layer 0 scan -> bufA (B,T,512) [fwd | bwd]
    scan_kernel<<<dim3(SPLIT, 2 * BATCH), STH>>>(gi, w_hh0f, b_hh0f, w_hh0b, b_hh0b, bufA);

    // layer 1 input gates (K = 512)
    gemm_kernel<<<gemm_grid, 256>>>(bufA, w_ih1f, b_ih1f, gi,                        M_ROWS, G3, 2 * HID, 0);
    gemm_kernel<<<gemm_grid, 256>>>(bufA, w_ih1b, b_ih1b, gi + (size_t)M_ROWS * G3,  M_ROWS, G3, 2 * HID, 0);

    // layer 1 scan -> bufB (B,T,512)
    scan_kernel<<<dim3(SPLIT, 2 * BATCH), STH>>>(gi, w_hh1f, b_hh1f, w_hh1b, b_hh1b, bufB);

    // sum dirs + LayerNorm -> bufC (32768,256)
    sum_ln_kernel<<<M_ROWS / 8, 256>>>(bufB, ln_g, ln_b, bufC);

    // FFN: mid = relu(ln @ w1^T + b1) -> bufA (32768,512)
    gemm_kernel<<<dim3(512 / 128, M_ROWS / 128), 256>>>(bufC, w1, b1, bufA, M_ROWS, 512, 256, 1);
    // y = mid @ w2^T + b2 -> gi (reused, 32768,256)
    gemm_kernel<<<dim3(256 / 128, M_ROWS / 128), 256>>>(bufA, w2, b2, gi,   M_ROWS, 256, 512, 0);

    // y (B,T,C) -> out (B,C,L)
    transpose_k<<<dim3(CH / 32, SEQ / 32, BATCH), tb>>>(gi, (float*)d_out, SEQ, CH);
}